// round 3
// baseline (speedup 1.0000x reference)
#include <cuda_runtime.h>
#include <cuda_bf16.h>

// Problem constants
#define BB   32
#define RR   2048
#define CIN  64
#define COUT 64
#define KK   16

// Scratch (device globals; no runtime allocation)
__device__ float d_priors[(size_t)KK * BB * RR * COUT];   // 268 MB [K][B][R][COUT]
__device__ float d_logits[KK * BB * RR];                  // 4 MB
__device__ float d_outA[KK * BB * COUT];
__device__ float d_outB[KK * BB * COUT];

// ---- packed f32x2 helpers --------------------------------------------------
__device__ __forceinline__ unsigned long long pk(float lo, float hi) {
    unsigned long long r;
    asm("mov.b64 %0, {%1, %2};" : "=l"(r) : "f"(lo), "f"(hi));
    return r;
}
__device__ __forceinline__ float2 upk(unsigned long long v) {
    float2 f;
    asm("mov.b64 {%0, %1}, %2;" : "=f"(f.x), "=f"(f.y) : "l"(v));
    return f;
}
__device__ __forceinline__ void fma2(unsigned long long& d, unsigned long long a,
                                     unsigned long long b) {
    asm("fma.rn.f32x2 %0, %1, %2, %0;" : "+l"(d) : "l"(a), "l"(b));
}

// ---- GEMM: priors[k][b][r][o] = sum_c x[b][r][c] * W[k][r][c][o] -----------
// Block = (k, 2 consecutive r). 256 threads = 2 groups of 128 (one per r).
// Thread tile: 4b x 4o (8 f32x2 accumulators).
// X is staged in smem PRE-DUPLICATED as {v,v} f32x2 pairs so the mainloop has
// no duplication MOVs: per c = 3x LDS.128 + 8 FFMA2.
// Smem per r-group: W 16384 B ([c][o]) + Xdup 64*68 floats = 17408 B.
// Total 2 * 33792 = 67584 B -> 3 blocks/SM.
#define GSM_FLTS 8448   // per-group floats: 4096 (W) + 4352 (Xdup, stride 68)

__global__ void __launch_bounds__(256, 3)
gemm_kernel(const float* __restrict__ x, const float* __restrict__ W) {
    extern __shared__ float sm[];
    const int tid = threadIdx.x;
    const int g   = tid >> 7;           // r within block
    const int t   = tid & 127;
    const int k   = blockIdx.y;
    const int r   = (blockIdx.x << 1) + g;

    float* Wsm = sm + g * GSM_FLTS;          // [c][o] 64x64
    float* Xsm = sm + g * GSM_FLTS + 4096;   // [c][b-pair dup] stride 68 floats

    // Load W[k][r] (64x64) -> smem, coalesced float4 (8 per thread)
    {
        const float4* Wg = (const float4*)(W + (((size_t)k * RR + r) << 12));
        float4* Wd = (float4*)Wsm;
#pragma unroll
        for (int i = 0; i < 8; i++) Wd[(i << 7) + t] = Wg[(i << 7) + t];
    }
    // Load x[:, r, :] -> smem transposed [c][b], each value duplicated to f32x2
    {
#pragma unroll
        for (int j = 0; j < 16; j++) {
            int idx = (j << 7) + t;     // 0..2047
            int b = idx >> 6, c = idx & 63;
            float v = x[(size_t)b * (RR * CIN) + ((size_t)r << 6) + c];
            *(float2*)(Xsm + c * 68 + 2 * b) = make_float2(v, v);
        }
    }
    __syncthreads();

    const int b0 = (t & 7) << 2;        // 4 consecutive b
    const int o0 = (t >> 3) << 2;       // 4 consecutive o
    const float* Wr = Wsm + o0;
    const float* Xr = Xsm + 2 * b0;

    unsigned long long acc[4][2];
#pragma unroll
    for (int i = 0; i < 4; i++) { acc[i][0] = 0ULL; acc[i][1] = 0ULL; }

#pragma unroll 8
    for (int c = 0; c < 64; c++) {
        float4 xv0 = *(const float4*)(Xr + c * 68);       // dup pairs b0, b0+1
        float4 xv1 = *(const float4*)(Xr + c * 68 + 4);   // dup pairs b0+2, b0+3
        float4 wv  = *(const float4*)(Wr + (c << 6));
        unsigned long long w0 = pk(wv.x, wv.y), w1 = pk(wv.z, wv.w);
        unsigned long long xd0 = pk(xv0.x, xv0.y), xd1 = pk(xv0.z, xv0.w);
        unsigned long long xd2 = pk(xv1.x, xv1.y), xd3 = pk(xv1.z, xv1.w);
        fma2(acc[0][0], xd0, w0); fma2(acc[0][1], xd0, w1);
        fma2(acc[1][0], xd1, w0); fma2(acc[1][1], xd1, w1);
        fma2(acc[2][0], xd2, w0); fma2(acc[2][1], xd2, w1);
        fma2(acc[3][0], xd3, w0); fma2(acc[3][1], xd3, w1);
    }

    // Direct stores: per instruction each warp covers 64B-contiguous chunks per
    // (b,r) row (full 32B sectors) -> sector-efficient.
#pragma unroll
    for (int i = 0; i < 4; i++) {
        float2 a0 = upk(acc[i][0]), a1 = upk(acc[i][1]);
        float* dst = d_priors + ((((size_t)k * BB + (b0 + i)) * RR + r) << 6) + o0;
        *(float4*)dst = make_float4(a0.x, a0.y, a1.x, a1.y);
    }
}

// ---- Routing passes --------------------------------------------------------
// PHASE 0: uniform weights -> outA = squash(mean_r prior)       (no shuffles)
// PHASE 1: l_r = dot(prior_r, outA); store logits; outB = squash(softmax-sum)
// PHASE 2: l_r = logits_r + dot(prior_r, outB); final -> d_out
// Block per (k,b), 512 threads = 16 warps. Warp w handles rows r === w (mod 16),
// 4 rows per iteration (4 independent shuffle chains for ILP + MLP).
// Lane l owns outputs o = 2l, 2l+1. exp is safe unshifted: |logit| <~ 6.5.
template <int PHASE>
__global__ void __launch_bounds__(512)
route_kernel(float* __restrict__ outFinal) {
    const int kb  = blockIdx.x;            // k*32 + b
    const int tid = threadIdx.x;
    const int w   = tid >> 5;
    const int l   = tid & 31;

    __shared__ float sOut[64];
    __shared__ float sS[16][64];
    __shared__ float sZ[16];
    __shared__ float sV[64];
    __shared__ float sScale;

    if (PHASE > 0 && tid < 64)
        sOut[tid] = (PHASE == 1 ? d_outA : d_outB)[kb * 64 + tid];
    __syncthreads();

    float2 o2 = make_float2(0.f, 0.f);
    if (PHASE > 0) o2 = *(float2*)&sOut[l * 2];

    const float2* P = (const float2*)d_priors + (size_t)kb * (RR * 32);
    const float*  L = d_logits + kb * RR;

    float sx = 0.f, sy = 0.f, Z = 0.f;
#pragma unroll 2
    for (int m = 0; m < 32; m++) {
        const int rb = w + (m << 6);       // rows rb, rb+16, rb+32, rb+48
        float2 p0 = P[(rb)      * 32 + l];
        float2 p1 = P[(rb + 16) * 32 + l];
        float2 p2 = P[(rb + 32) * 32 + l];
        float2 p3 = P[(rb + 48) * 32 + l];

        if (PHASE == 0) {
            sx += (p0.x + p1.x) + (p2.x + p3.x);
            sy += (p0.y + p1.y) + (p2.y + p3.y);
        } else {
            float d0 = p0.x * o2.x + p0.y * o2.y;
            float d1 = p1.x * o2.x + p1.y * o2.y;
            float d2 = p2.x * o2.x + p2.y * o2.y;
            float d3 = p3.x * o2.x + p3.y * o2.y;
#pragma unroll
            for (int msk = 16; msk; msk >>= 1) {
                d0 += __shfl_xor_sync(0xffffffffu, d0, msk);
                d1 += __shfl_xor_sync(0xffffffffu, d1, msk);
                d2 += __shfl_xor_sync(0xffffffffu, d2, msk);
                d3 += __shfl_xor_sync(0xffffffffu, d3, msk);
            }
            float w0, w1, w2, w3;
            if (PHASE == 1) {
                if (l < 4) {
                    float dv = (l == 0) ? d0 : (l == 1) ? d1 : (l == 2) ? d2 : d3;
                    d_logits[kb * RR + rb + (l << 4)] = dv;
                }
                w0 = __expf(d0); w1 = __expf(d1);
                w2 = __expf(d2); w3 = __expf(d3);
            } else {
                w0 = __expf(L[rb]      + d0);
                w1 = __expf(L[rb + 16] + d1);
                w2 = __expf(L[rb + 32] + d2);
                w3 = __expf(L[rb + 48] + d3);
            }
            sx += (w0 * p0.x + w1 * p1.x) + (w2 * p2.x + w3 * p3.x);
            sy += (w0 * p0.y + w1 * p1.y) + (w2 * p2.y + w3 * p3.y);
            Z  += (w0 + w1) + (w2 + w3);
        }
    }

    sS[w][2 * l]     = sx;
    sS[w][2 * l + 1] = sy;
    if (l == 0) sZ[w] = Z;
    __syncthreads();

    if (tid < 64) {
        float v = 0.f;
#pragma unroll
        for (int j = 0; j < 16; j++) v += sS[j][tid];
        float Zt;
        if (PHASE == 0) {
            Zt = (float)RR;
        } else {
            Zt = 0.f;
#pragma unroll
            for (int j = 0; j < 16; j++) Zt += sZ[j];
        }
        sV[tid] = v / Zt;
    }
    __syncthreads();

    if (tid < 32) {
        float a = sV[tid], b = sV[tid + 32];
        float sq = a * a + b * b;
#pragma unroll
        for (int msk = 16; msk; msk >>= 1) sq += __shfl_xor_sync(0xffffffffu, sq, msk);
        if (tid == 0) sScale = sqrtf(sq) / (1.f + sq);   // (sq/(1+sq))/sqrt(sq)
    }
    __syncthreads();

    if (tid < 64) {
        float* dst = (PHASE == 0) ? d_outA : (PHASE == 1) ? d_outB : outFinal;
        dst[kb * 64 + tid] = sV[tid] * sScale;
    }
}

extern "C" void kernel_launch(void* const* d_in, const int* in_sizes, int n_in,
                              void* d_out, int out_size) {
    const float* x = (const float*)d_in[0];
    const float* W = (const float*)d_in[1];
    if (in_sizes[0] > in_sizes[1]) {  // defensive: x is the smaller tensor
        const float* t = x; x = W; W = t;
    }

    // Dynamic smem > 48KB needs opt-in (host-side attribute, capture-safe)
    cudaFuncSetAttribute(gemm_kernel, cudaFuncAttributeMaxDynamicSharedMemorySize, 67584);

    gemm_kernel<<<dim3(RR / 2, KK, 1), 256, 67584>>>(x, W);
    route_kernel<0><<<KK * BB, 512>>>(nullptr);
    route_kernel<1><<<KK * BB, 512>>>(nullptr);
    route_kernel<2><<<KK * BB, 512>>>((float*)d_out);
}

// round 7
// speedup vs baseline: 1.4916x; 1.4916x over previous
#include <cuda_runtime.h>
#include <cuda_bf16.h>
#include <cstdint>

// Problem constants
#define BB   32
#define RR   2048
#define CIN  64
#define COUT 64
#define KK   16

// Scratch (device globals; no runtime allocation)
__device__ float d_priors[(size_t)KK * BB * RR * COUT];   // 268 MB [K][B][R][COUT]
__device__ float d_logits[KK * BB * RR];                  // 4 MB
__device__ float d_outA[KK * BB * COUT];
__device__ float d_outB[KK * BB * COUT];

// ---- helpers ----------------------------------------------------------------
__device__ __forceinline__ float2 upk(unsigned long long v) {
    float2 f;
    asm("mov.b64 {%0, %1}, %2;" : "=f"(f.x), "=f"(f.y) : "l"(v));
    return f;
}
__device__ __forceinline__ void fma2(unsigned long long& d, unsigned long long a,
                                     unsigned long long b) {
    asm("fma.rn.f32x2 %0, %1, %2, %0;" : "+l"(d) : "l"(a), "l"(b));
}
__device__ __forceinline__ uint32_t smem_u32(const void* p) {
    uint32_t a;
    asm("{ .reg .u64 t; cvta.to.shared.u64 t, %1; cvt.u32.u64 %0, t; }"
        : "=r"(a) : "l"(p));
    return a;
}
__device__ __forceinline__ void cp16(uint32_t s, const void* g) {
    asm volatile("cp.async.cg.shared.global [%0], [%1], 16;" :: "r"(s), "l"(g));
}
#define CP_COMMIT() asm volatile("cp.async.commit_group;")
#define CP_WAIT1()  asm volatile("cp.async.wait_group 1;")

// ---- GEMM: priors[k][b][r][o] = sum_c x[b][r][c] * W[k][r][c][o] -----------
// Block = 2 consecutive r, looping over ALL 16 k. 128 threads = 2 groups of 64.
// Thread tile 4b x 8o -> 16 f32x2 accumulators.
// Smem (floats): Xdup[2 g][64 c][68 pad]  (x duplicated {v,v})   = 34816 B
//                Wbuf[2 buf][2 g][64 c][64 o]                    = 65536 B
// x loaded ONCE per block; W double-buffered via cp.async across the k loop.
// Mainloop per c: 4x LDS.128 (ulonglong2) + 16 FFMA2, no MOVs -> FMA-pipe bound.
// Xdup row stride 68 floats (272B): 16B-aligned for LDS.128, staging STS.64
// conflict degree 4 instead of 32.
#define XSTRIDE 68
#define XG      (64 * XSTRIDE)        // 4352 floats per r-group
#define WF      (2 * XG)              // 8704 floats: W buffers start here

__global__ void __launch_bounds__(128, 2)
gemm_kernel(const float* __restrict__ x, const float* __restrict__ W) {
    extern __shared__ float sm[];
    const int tid = threadIdx.x;
    const int g   = tid >> 6;
    const int t   = tid & 63;
    const int r0  = blockIdx.x << 1;      // this block's first r

    const uint32_t smW = smem_u32(sm + WF);

    // ---- load x for both r's (coalesced LDG), store duplicated {v,v} ----
#pragma unroll
    for (int i = 0; i < 32; i++) {
        int idx = (i << 7) + tid;         // 0..4095
        int gg  = idx >> 11;
        int rem = idx & 2047;
        int b   = rem >> 6, c = rem & 63;
        float v = x[(size_t)b * (RR * CIN) + (size_t)(r0 + gg) * CIN + c];
        *(float2*)(sm + gg * XG + c * XSTRIDE + 2 * b) = make_float2(v, v);
    }

    // ---- prefetch W[k=0] into buf 0 (cp.async group #0) ----
    {
        const float* Wk = W + ((size_t)r0 << 12);   // k=0: tiles r0, r0+1
#pragma unroll
        for (int j = tid; j < 2048; j += 128) {
            int gg = j >> 10, off = j & 1023;       // off = 16B chunk in 64x64 tile
            cp16(smW + gg * 16384 + off * 16,
                 Wk + ((size_t)gg << 12) + ((size_t)off << 2));
        }
    }
    CP_COMMIT();

    const int b0 = (t & 7) << 2;          // 4 consecutive b
    const int o0 = (t >> 3) << 3;         // 8 consecutive o
    const float* Xr = sm + g * XG + 2 * b0;

#pragma unroll 1
    for (int k = 0; k < KK; k++) {
        const int p = k & 1;
        // prefetch next k into the other buffer (group #(k+1))
        if (k + 1 < KK) {
            const float* Wk = W + (((size_t)(k + 1) * RR + r0) << 12);
#pragma unroll
            for (int j = tid; j < 2048; j += 128) {
                int gg = j >> 10, off = j & 1023;
                cp16(smW + (p ^ 1) * 32768 + gg * 16384 + off * 16,
                     Wk + ((size_t)gg << 12) + ((size_t)off << 2));
            }
        }
        CP_COMMIT();
        CP_WAIT1();                       // group #k complete -> buf p ready
        __syncthreads();

        const float* Wr = sm + WF + (p << 13) + (g << 12) + o0;

        unsigned long long acc[4][4];
#pragma unroll
        for (int i = 0; i < 4; i++)
#pragma unroll
            for (int j = 0; j < 4; j++) acc[i][j] = 0ULL;

#pragma unroll 8
        for (int c = 0; c < 64; c++) {
            ulonglong2 xlo = *(const ulonglong2*)(Xr + c * XSTRIDE);      // b0,b0+1
            ulonglong2 xhi = *(const ulonglong2*)(Xr + c * XSTRIDE + 4);  // b0+2,b0+3
            ulonglong2 wA  = *(const ulonglong2*)(Wr + (c << 6));         // o0..o0+3
            ulonglong2 wB  = *(const ulonglong2*)(Wr + (c << 6) + 4);     // o0+4..+7
            fma2(acc[0][0], xlo.x, wA.x); fma2(acc[0][1], xlo.x, wA.y);
            fma2(acc[0][2], xlo.x, wB.x); fma2(acc[0][3], xlo.x, wB.y);
            fma2(acc[1][0], xlo.y, wA.x); fma2(acc[1][1], xlo.y, wA.y);
            fma2(acc[1][2], xlo.y, wB.x); fma2(acc[1][3], xlo.y, wB.y);
            fma2(acc[2][0], xhi.x, wA.x); fma2(acc[2][1], xhi.x, wA.y);
            fma2(acc[2][2], xhi.x, wB.x); fma2(acc[2][3], xhi.x, wB.y);
            fma2(acc[3][0], xhi.y, wA.x); fma2(acc[3][1], xhi.y, wA.y);
            fma2(acc[3][2], xhi.y, wB.x); fma2(acc[3][3], xhi.y, wB.y);
        }

        // store priors for this k: [K][B][R][O]; per (b,r) row a warp covers
        // 256B contiguous -> full sectors.
#pragma unroll
        for (int i = 0; i < 4; i++) {
            float2 a0 = upk(acc[i][0]), a1 = upk(acc[i][1]);
            float2 a2 = upk(acc[i][2]), a3 = upk(acc[i][3]);
            float* dst = d_priors +
                ((((size_t)k * BB + (b0 + i)) * RR + (r0 + g)) << 6) + o0;
            *(float4*)dst       = make_float4(a0.x, a0.y, a1.x, a1.y);
            *(float4*)(dst + 4) = make_float4(a2.x, a2.y, a3.x, a3.y);
        }
        __syncthreads();   // all reads of buf p done before refill at k+2
    }
}

// ---- Routing passes (validated R3: route<2> 52.7us, DRAM 66%, occ 84%) ------
// PHASE 0: uniform weights -> outA = squash(mean_r prior)       (no shuffles)
// PHASE 1: l_r = dot(prior_r, outA); store logits; outB = squash(softmax-sum)
// PHASE 2: l_r = logits_r + dot(prior_r, outB); final -> d_out
// Block per (k,b), 512 threads = 16 warps; warp handles 4 rows/iter.
template <int PHASE>
__global__ void __launch_bounds__(512)
route_kernel(float* __restrict__ outFinal) {
    const int kb  = blockIdx.x;            // k*32 + b
    const int tid = threadIdx.x;
    const int w   = tid >> 5;
    const int l   = tid & 31;

    __shared__ float sOut[64];
    __shared__ float sS[16][64];
    __shared__ float sZ[16];
    __shared__ float sV[64];
    __shared__ float sScale;

    if (PHASE > 0 && tid < 64)
        sOut[tid] = (PHASE == 1 ? d_outA : d_outB)[kb * 64 + tid];
    __syncthreads();

    float2 o2 = make_float2(0.f, 0.f);
    if (PHASE > 0) o2 = *(float2*)&sOut[l * 2];

    const float2* P = (const float2*)d_priors + (size_t)kb * (RR * 32);
    const float*  L = d_logits + kb * RR;

    float sx = 0.f, sy = 0.f, Z = 0.f;
#pragma unroll 2
    for (int m = 0; m < 32; m++) {
        const int rb = w + (m << 6);       // rows rb, rb+16, rb+32, rb+48
        float2 p0 = P[(rb)      * 32 + l];
        float2 p1 = P[(rb + 16) * 32 + l];
        float2 p2 = P[(rb + 32) * 32 + l];
        float2 p3 = P[(rb + 48) * 32 + l];

        if (PHASE == 0) {
            sx += (p0.x + p1.x) + (p2.x + p3.x);
            sy += (p0.y + p1.y) + (p2.y + p3.y);
        } else {
            float d0 = p0.x * o2.x + p0.y * o2.y;
            float d1 = p1.x * o2.x + p1.y * o2.y;
            float d2 = p2.x * o2.x + p2.y * o2.y;
            float d3 = p3.x * o2.x + p3.y * o2.y;
#pragma unroll
            for (int msk = 16; msk; msk >>= 1) {
                d0 += __shfl_xor_sync(0xffffffffu, d0, msk);
                d1 += __shfl_xor_sync(0xffffffffu, d1, msk);
                d2 += __shfl_xor_sync(0xffffffffu, d2, msk);
                d3 += __shfl_xor_sync(0xffffffffu, d3, msk);
            }
            float w0, w1, w2, w3;
            if (PHASE == 1) {
                if (l < 4) {
                    float dv = (l == 0) ? d0 : (l == 1) ? d1 : (l == 2) ? d2 : d3;
                    d_logits[kb * RR + rb + (l << 4)] = dv;
                }
                w0 = __expf(d0); w1 = __expf(d1);
                w2 = __expf(d2); w3 = __expf(d3);
            } else {
                w0 = __expf(L[rb]      + d0);
                w1 = __expf(L[rb + 16] + d1);
                w2 = __expf(L[rb + 32] + d2);
                w3 = __expf(L[rb + 48] + d3);
            }
            sx += (w0 * p0.x + w1 * p1.x) + (w2 * p2.x + w3 * p3.x);
            sy += (w0 * p0.y + w1 * p1.y) + (w2 * p2.y + w3 * p3.y);
            Z  += (w0 + w1) + (w2 + w3);
        }
    }

    sS[w][2 * l]     = sx;
    sS[w][2 * l + 1] = sy;
    if (l == 0) sZ[w] = Z;
    __syncthreads();

    if (tid < 64) {
        float v = 0.f;
#pragma unroll
        for (int j = 0; j < 16; j++) v += sS[j][tid];
        float Zt;
        if (PHASE == 0) {
            Zt = (float)RR;
        } else {
            Zt = 0.f;
#pragma unroll
            for (int j = 0; j < 16; j++) Zt += sZ[j];
        }
        sV[tid] = v / Zt;
    }
    __syncthreads();

    if (tid < 32) {
        float a = sV[tid], b = sV[tid + 32];
        float sq = a * a + b * b;
#pragma unroll
        for (int msk = 16; msk; msk >>= 1) sq += __shfl_xor_sync(0xffffffffu, sq, msk);
        if (tid == 0) sScale = sqrtf(sq) / (1.f + sq);   // (sq/(1+sq))/sqrt(sq)
    }
    __syncthreads();

    if (tid < 64) {
        float* dst = (PHASE == 0) ? d_outA : (PHASE == 1) ? d_outB : outFinal;
        dst[kb * 64 + tid] = sV[tid] * sScale;
    }
}

extern "C" void kernel_launch(void* const* d_in, const int* in_sizes, int n_in,
                              void* d_out, int out_size) {
    const float* x = (const float*)d_in[0];
    const float* W = (const float*)d_in[1];
    if (in_sizes[0] > in_sizes[1]) {  // defensive: x is the smaller tensor
        const float* t = x; x = W; W = t;
    }

    // 100352B dynamic smem needs opt-in (host-side attribute, capture-safe)
    cudaFuncSetAttribute(gemm_kernel, cudaFuncAttributeMaxDynamicSharedMemorySize, 100352);

    gemm_kernel<<<RR / 2, 128, 100352>>>(x, W);
    route_kernel<0><<<KK * BB, 512>>>(nullptr);
    route_kernel<1><<<KK * BB, 512>>>(nullptr);
    route_kernel<2><<<KK * BB, 512>>>((float*)d_out);
}

// round 9
// speedup vs baseline: 1.6590x; 1.1122x over previous
#include <cuda_runtime.h>
#include <cuda_bf16.h>
#include <cstdint>

// Problem constants
#define BB   32
#define RR   2048
#define CIN  64
#define COUT 64
#define KK   16

// Scratch (device globals; no runtime allocation)
__device__ float d_priors[(size_t)KK * BB * RR * COUT];   // 268 MB [K][B][R][COUT]
__device__ float d_logits[KK * BB * RR];                  // 4 MB
__device__ float d_outA[KK * BB * COUT];
__device__ float d_outB[KK * BB * COUT];

// ---- helpers ----------------------------------------------------------------
__device__ __forceinline__ float2 upk(unsigned long long v) {
    float2 f;
    asm("mov.b64 {%0, %1}, %2;" : "=f"(f.x), "=f"(f.y) : "l"(v));
    return f;
}
__device__ __forceinline__ void fma2(unsigned long long& d, unsigned long long a,
                                     unsigned long long b) {
    asm("fma.rn.f32x2 %0, %1, %2, %0;" : "+l"(d) : "l"(a), "l"(b));
}
__device__ __forceinline__ uint32_t smem_u32(const void* p) {
    uint32_t a;
    asm("{ .reg .u64 t; cvta.to.shared.u64 t, %1; cvt.u32.u64 %0, t; }"
        : "=r"(a) : "l"(p));
    return a;
}
__device__ __forceinline__ void cp16(uint32_t s, const void* g) {
    asm volatile("cp.async.cg.shared.global [%0], [%1], 16;" :: "r"(s), "l"(g));
}
#define CP_COMMIT() asm volatile("cp.async.commit_group;")
#define CP_WAIT1()  asm volatile("cp.async.wait_group 1;")

// ---- GEMM: priors[k][b][r][o] = sum_c x[b][r][c] * W[k][r][c][o] -----------
// Block = ONE r, looping over all 16 k. 128 threads, thread tile 2b x 8o
// (8 f32x2 accumulators). 4 blocks/SM (smem 50176B) -> 4 warps/SMSP: latency,
// barrier drains and cp.async waits hidden by cross-block warps.
// Smem (floats): Xdup[64 c][68 pad]  (x duplicated {v,v})  = 17408 B
//                Wbuf[2 buf][64 c][64 o]                   = 32768 B
// x loaded ONCE per block; W double-buffered via cp.async across the k loop.
// Mainloop per c: 3x LDS.128 + 8 FFMA2 (11 issues / 16 pipe-cycles).
#define XSTRIDE 68
#define WF      (64 * XSTRIDE)        // 4352 floats: W buffers start here
#define GEMM_SMEM ((WF + 2 * 4096) * 4)   // 50176 bytes

__global__ void __launch_bounds__(128, 4)
gemm_kernel(const float* __restrict__ x, const float* __restrict__ W) {
    extern __shared__ float sm[];
    const int tid = threadIdx.x;
    const int r   = blockIdx.x;

    const uint32_t smW = smem_u32(sm + WF);

    // ---- load x[:, r, :] (coalesced), store duplicated {v,v} ----
#pragma unroll
    for (int i = 0; i < 16; i++) {
        int idx = (i << 7) + tid;         // 0..2047
        int b = idx >> 6, c = idx & 63;
        float v = x[(size_t)b * (RR * CIN) + (size_t)r * CIN + c];
        *(float2*)(sm + c * XSTRIDE + 2 * b) = make_float2(v, v);
    }

    // ---- prefetch W[k=0][r] into buf 0 (cp.async group #0) ----
    {
        const float* Wk = W + ((size_t)r << 12);
#pragma unroll
        for (int j = tid; j < 1024; j += 128)
            cp16(smW + j * 16, Wk + ((size_t)j << 2));
    }
    CP_COMMIT();

    const int b0 = (tid & 15) << 1;       // 2 consecutive b
    const int o0 = (tid >> 4) << 3;       // 8 consecutive o
    const float* Xr = sm + 2 * b0;

#pragma unroll 1
    for (int k = 0; k < KK; k++) {
        const int p = k & 1;
        // prefetch next k into the other buffer (group #(k+1))
        if (k + 1 < KK) {
            const float* Wk = W + (((size_t)(k + 1) * RR + r) << 12);
#pragma unroll
            for (int j = tid; j < 1024; j += 128)
                cp16(smW + (p ^ 1) * 16384 + j * 16, Wk + ((size_t)j << 2));
        }
        CP_COMMIT();
        CP_WAIT1();                       // group #k complete -> buf p ready
        __syncthreads();

        const float* Wr = sm + WF + (p << 12) + o0;

        unsigned long long acc[2][4];
#pragma unroll
        for (int i = 0; i < 2; i++)
#pragma unroll
            for (int j = 0; j < 4; j++) acc[i][j] = 0ULL;

#pragma unroll 8
        for (int c = 0; c < 64; c++) {
            ulonglong2 xv = *(const ulonglong2*)(Xr + c * XSTRIDE);  // dup b0, b0+1
            ulonglong2 wA = *(const ulonglong2*)(Wr + (c << 6));     // o0..o0+3
            ulonglong2 wB = *(const ulonglong2*)(Wr + (c << 6) + 4); // o0+4..+7
            fma2(acc[0][0], xv.x, wA.x); fma2(acc[0][1], xv.x, wA.y);
            fma2(acc[0][2], xv.x, wB.x); fma2(acc[0][3], xv.x, wB.y);
            fma2(acc[1][0], xv.y, wA.x); fma2(acc[1][1], xv.y, wA.y);
            fma2(acc[1][2], xv.y, wB.x); fma2(acc[1][3], xv.y, wB.y);
        }

        // store priors for this k: [K][B][R][O]
#pragma unroll
        for (int i = 0; i < 2; i++) {
            float2 a0 = upk(acc[i][0]), a1 = upk(acc[i][1]);
            float2 a2 = upk(acc[i][2]), a3 = upk(acc[i][3]);
            float* dst = d_priors +
                ((((size_t)k * BB + (b0 + i)) * RR + r) << 6) + o0;
            *(float4*)dst       = make_float4(a0.x, a0.y, a1.x, a1.y);
            *(float4*)(dst + 4) = make_float4(a2.x, a2.y, a3.x, a3.y);
        }
        __syncthreads();   // all reads of buf p done before refill at k+2
    }
}

// ---- Routing passes (validated R3/R7: route<2> ~52us, DRAM 67%, occ 83%) ----
// PHASE 0: uniform weights -> outA = squash(mean_r prior)       (no shuffles)
// PHASE 1: l_r = dot(prior_r, outA); store logits; outB = squash(softmax-sum)
// PHASE 2: l_r = logits_r + dot(prior_r, outB); final -> d_out
// Block per (k,b), 512 threads = 16 warps; warp handles 4 rows/iter.
template <int PHASE>
__global__ void __launch_bounds__(512)
route_kernel(float* __restrict__ outFinal) {
    const int kb  = blockIdx.x;            // k*32 + b
    const int tid = threadIdx.x;
    const int w   = tid >> 5;
    const int l   = tid & 31;

    __shared__ float sOut[64];
    __shared__ float sS[16][64];
    __shared__ float sZ[16];
    __shared__ float sV[64];
    __shared__ float sScale;

    if (PHASE > 0 && tid < 64)
        sOut[tid] = (PHASE == 1 ? d_outA : d_outB)[kb * 64 + tid];
    __syncthreads();

    float2 o2 = make_float2(0.f, 0.f);
    if (PHASE > 0) o2 = *(float2*)&sOut[l * 2];

    const float2* P = (const float2*)d_priors + (size_t)kb * (RR * 32);
    const float*  L = d_logits + kb * RR;

    float sx = 0.f, sy = 0.f, Z = 0.f;
#pragma unroll 2
    for (int m = 0; m < 32; m++) {
        const int rb = w + (m << 6);       // rows rb, rb+16, rb+32, rb+48
        float2 p0 = P[(rb)      * 32 + l];
        float2 p1 = P[(rb + 16) * 32 + l];
        float2 p2 = P[(rb + 32) * 32 + l];
        float2 p3 = P[(rb + 48) * 32 + l];

        if (PHASE == 0) {
            sx += (p0.x + p1.x) + (p2.x + p3.x);
            sy += (p0.y + p1.y) + (p2.y + p3.y);
        } else {
            float d0 = p0.x * o2.x + p0.y * o2.y;
            float d1 = p1.x * o2.x + p1.y * o2.y;
            float d2 = p2.x * o2.x + p2.y * o2.y;
            float d3 = p3.x * o2.x + p3.y * o2.y;
#pragma unroll
            for (int msk = 16; msk; msk >>= 1) {
                d0 += __shfl_xor_sync(0xffffffffu, d0, msk);
                d1 += __shfl_xor_sync(0xffffffffu, d1, msk);
                d2 += __shfl_xor_sync(0xffffffffu, d2, msk);
                d3 += __shfl_xor_sync(0xffffffffu, d3, msk);
            }
            float w0, w1, w2, w3;
            if (PHASE == 1) {
                if (l < 4) {
                    float dv = (l == 0) ? d0 : (l == 1) ? d1 : (l == 2) ? d2 : d3;
                    d_logits[kb * RR + rb + (l << 4)] = dv;
                }
                w0 = __expf(d0); w1 = __expf(d1);
                w2 = __expf(d2); w3 = __expf(d3);
            } else {
                w0 = __expf(L[rb]      + d0);
                w1 = __expf(L[rb + 16] + d1);
                w2 = __expf(L[rb + 32] + d2);
                w3 = __expf(L[rb + 48] + d3);
            }
            sx += (w0 * p0.x + w1 * p1.x) + (w2 * p2.x + w3 * p3.x);
            sy += (w0 * p0.y + w1 * p1.y) + (w2 * p2.y + w3 * p3.y);
            Z  += (w0 + w1) + (w2 + w3);
        }
    }

    sS[w][2 * l]     = sx;
    sS[w][2 * l + 1] = sy;
    if (l == 0) sZ[w] = Z;
    __syncthreads();

    if (tid < 64) {
        float v = 0.f;
#pragma unroll
        for (int j = 0; j < 16; j++) v += sS[j][tid];
        float Zt;
        if (PHASE == 0) {
            Zt = (float)RR;
        } else {
            Zt = 0.f;
#pragma unroll
            for (int j = 0; j < 16; j++) Zt += sZ[j];
        }
        sV[tid] = v / Zt;
    }
    __syncthreads();

    if (tid < 32) {
        float a = sV[tid], b = sV[tid + 32];
        float sq = a * a + b * b;
#pragma unroll
        for (int msk = 16; msk; msk >>= 1) sq += __shfl_xor_sync(0xffffffffu, sq, msk);
        if (tid == 0) sScale = sqrtf(sq) / (1.f + sq);   // (sq/(1+sq))/sqrt(sq)
    }
    __syncthreads();

    if (tid < 64) {
        float* dst = (PHASE == 0) ? d_outA : (PHASE == 1) ? d_outB : outFinal;
        dst[kb * 64 + tid] = sV[tid] * sScale;
    }
}

extern "C" void kernel_launch(void* const* d_in, const int* in_sizes, int n_in,
                              void* d_out, int out_size) {
    const float* x = (const float*)d_in[0];
    const float* W = (const float*)d_in[1];
    if (in_sizes[0] > in_sizes[1]) {  // defensive: x is the smaller tensor
        const float* t = x; x = W; W = t;
    }

    // >48KB dynamic smem needs opt-in (host-side attribute, capture-safe)
    cudaFuncSetAttribute(gemm_kernel, cudaFuncAttributeMaxDynamicSharedMemorySize, GEMM_SMEM);

    gemm_kernel<<<RR, 128, GEMM_SMEM>>>(x, W);
    route_kernel<0><<<KK * BB, 512>>>(nullptr);
    route_kernel<1><<<KK * BB, 512>>>(nullptr);
    route_kernel<2><<<KK * BB, 512>>>((float*)d_out);
}

// round 16
// speedup vs baseline: 1.6757x; 1.0100x over previous
#include <cuda_runtime.h>
#include <cuda_bf16.h>
#include <cstdint>

// Problem constants
#define BB   32
#define RR   2048
#define CIN  64
#define COUT 64
#define KK   16

// Scratch (device globals; no runtime allocation)
__device__ float d_priors[(size_t)KK * BB * RR * COUT];   // 268 MB [K][B][R][COUT]
__device__ float d_logits[KK * BB * RR];                  // 4 MB
__device__ float d_outA[KK * BB * COUT];
__device__ float d_outB[KK * BB * COUT];

// ---- helpers ----------------------------------------------------------------
__device__ __forceinline__ float2 upk(unsigned long long v) {
    float2 f;
    asm("mov.b64 {%0, %1}, %2;" : "=f"(f.x), "=f"(f.y) : "l"(v));
    return f;
}
__device__ __forceinline__ void fma2(unsigned long long& d, unsigned long long a,
                                     unsigned long long b) {
    asm("fma.rn.f32x2 %0, %1, %2, %0;" : "+l"(d) : "l"(a), "l"(b));
}
__device__ __forceinline__ uint32_t smem_u32(const void* p) {
    uint32_t a;
    asm("{ .reg .u64 t; cvta.to.shared.u64 t, %1; cvt.u32.u64 %0, t; }"
        : "=r"(a) : "l"(p));
    return a;
}
__device__ __forceinline__ void cp16(uint32_t s, const void* g) {
    asm volatile("cp.async.cg.shared.global [%0], [%1], 16;" :: "r"(s), "l"(g));
}
#define CP_COMMIT() asm volatile("cp.async.commit_group;")
#define CP_WAIT1()  asm volatile("cp.async.wait_group 1;")

// Empty kernel: shifts ncu's sampled launch index (-s 5) onto gemm_kernel.
// Stream order: [memset, memset, dummy x3, gemm, r0, r1, r2] -> index 5 = gemm.
__global__ void dummy_kernel() {}

// ---- GEMM: priors[k][b][r][o] = sum_c x[b][r][c] * W[k][r][c][o] -----------
// Block = (one r, 8 consecutive k). 128 threads, thread tile 2b x 8o
// (8 f32x2 accumulators). 4 blocks/SM (smem 50176B) -> 4 warps/SMSP.
// Grid (2048, 2): k-half split halves the wave-quantization tail vs a single
// 16-k loop (4096 blocks / 592 slots = 6.9 waves, ~7% tail vs 13%).
// Smem (floats): Xdup[64 c][68 pad]  (x duplicated {v,v})  = 17408 B
//                Wbuf[2 buf][64 c][64 o]                   = 32768 B
// x loaded once per block; W double-buffered via cp.async across the k loop.
// Mainloop per c: 3x LDS.128 + 8 FFMA2 (fma-pipe-bound).
#define XSTRIDE 68
#define WF      (64 * XSTRIDE)        // 4352 floats: W buffers start here
#define GEMM_SMEM ((WF + 2 * 4096) * 4)   // 50176 bytes
#define KSPLIT 8                      // k's per block

__global__ void __launch_bounds__(128, 4)
gemm_kernel(const float* __restrict__ x, const float* __restrict__ W) {
    extern __shared__ float sm[];
    const int tid = threadIdx.x;
    const int r   = blockIdx.x;
    const int kb0 = blockIdx.y * KSPLIT;  // first k of this block

    const uint32_t smW = smem_u32(sm + WF);

    // ---- load x[:, r, :] (coalesced), store duplicated {v,v} ----
#pragma unroll
    for (int i = 0; i < 16; i++) {
        int idx = (i << 7) + tid;         // 0..2047
        int b = idx >> 6, c = idx & 63;
        float v = x[(size_t)b * (RR * CIN) + (size_t)r * CIN + c];
        *(float2*)(sm + c * XSTRIDE + 2 * b) = make_float2(v, v);
    }

    // ---- prefetch W[kb0][r] into buf 0 (cp.async group #0) ----
    {
        const float* Wk = W + (((size_t)kb0 * RR + r) << 12);
#pragma unroll
        for (int j = tid; j < 1024; j += 128)
            cp16(smW + j * 16, Wk + ((size_t)j << 2));
    }
    CP_COMMIT();

    const int b0 = (tid & 15) << 1;       // 2 consecutive b
    const int o0 = (tid >> 4) << 3;       // 8 consecutive o
    const float* Xr = sm + 2 * b0;

#pragma unroll 1
    for (int kk = 0; kk < KSPLIT; kk++) {
        const int p = kk & 1;
        const int k = kb0 + kk;
        // prefetch next k into the other buffer (group #(kk+1))
        if (kk + 1 < KSPLIT) {
            const float* Wk = W + (((size_t)(k + 1) * RR + r) << 12);
#pragma unroll
            for (int j = tid; j < 1024; j += 128)
                cp16(smW + (p ^ 1) * 16384 + j * 16, Wk + ((size_t)j << 2));
        }
        CP_COMMIT();
        CP_WAIT1();                       // group #kk complete -> buf p ready
        __syncthreads();

        const float* Wr = sm + WF + (p << 12) + o0;

        unsigned long long acc[2][4];
#pragma unroll
        for (int i = 0; i < 2; i++)
#pragma unroll
            for (int j = 0; j < 4; j++) acc[i][j] = 0ULL;

#pragma unroll 8
        for (int c = 0; c < 64; c++) {
            ulonglong2 xv = *(const ulonglong2*)(Xr + c * XSTRIDE);  // dup b0, b0+1
            ulonglong2 wA = *(const ulonglong2*)(Wr + (c << 6));     // o0..o0+3
            ulonglong2 wB = *(const ulonglong2*)(Wr + (c << 6) + 4); // o0+4..+7
            fma2(acc[0][0], xv.x, wA.x); fma2(acc[0][1], xv.x, wA.y);
            fma2(acc[0][2], xv.x, wB.x); fma2(acc[0][3], xv.x, wB.y);
            fma2(acc[1][0], xv.y, wA.x); fma2(acc[1][1], xv.y, wA.y);
            fma2(acc[1][2], xv.y, wB.x); fma2(acc[1][3], xv.y, wB.y);
        }

        // store priors for this k: [K][B][R][O]
#pragma unroll
        for (int i = 0; i < 2; i++) {
            float2 a0 = upk(acc[i][0]), a1 = upk(acc[i][1]);
            float2 a2 = upk(acc[i][2]), a3 = upk(acc[i][3]);
            float* dst = d_priors +
                ((((size_t)k * BB + (b0 + i)) * RR + r) << 6) + o0;
            *(float4*)dst       = make_float4(a0.x, a0.y, a1.x, a1.y);
            *(float4*)(dst + 4) = make_float4(a2.x, a2.y, a3.x, a3.y);
        }
        __syncthreads();   // all reads of buf p done before refill at kk+2
    }
}

// ---- Routing passes (validated R3/R7/R9: route<2> ~52us, DRAM ~66%) --------
// PHASE 0: uniform weights -> outA = squash(mean_r prior)       (no shuffles)
// PHASE 1: l_r = dot(prior_r, outA); store logits; outB = squash(softmax-sum)
// PHASE 2: l_r = logits_r + dot(prior_r, outB); final -> d_out
// Block per (k,b), 512 threads = 16 warps; warp handles 4 rows/iter.
template <int PHASE>
__global__ void __launch_bounds__(512)
route_kernel(float* __restrict__ outFinal) {
    const int kb  = blockIdx.x;            // k*32 + b
    const int tid = threadIdx.x;
    const int w   = tid >> 5;
    const int l   = tid & 31;

    __shared__ float sOut[64];
    __shared__ float sS[16][64];
    __shared__ float sZ[16];
    __shared__ float sV[64];
    __shared__ float sScale;

    if (PHASE > 0 && tid < 64)
        sOut[tid] = (PHASE == 1 ? d_outA : d_outB)[kb * 64 + tid];
    __syncthreads();

    float2 o2 = make_float2(0.f, 0.f);
    if (PHASE > 0) o2 = *(float2*)&sOut[l * 2];

    const float2* P = (const float2*)d_priors + (size_t)kb * (RR * 32);
    const float*  L = d_logits + kb * RR;

    float sx = 0.f, sy = 0.f, Z = 0.f;
#pragma unroll 2
    for (int m = 0; m < 32; m++) {
        const int rb = w + (m << 6);       // rows rb, rb+16, rb+32, rb+48
        float2 p0 = P[(rb)      * 32 + l];
        float2 p1 = P[(rb + 16) * 32 + l];
        float2 p2 = P[(rb + 32) * 32 + l];
        float2 p3 = P[(rb + 48) * 32 + l];

        if (PHASE == 0) {
            sx += (p0.x + p1.x) + (p2.x + p3.x);
            sy += (p0.y + p1.y) + (p2.y + p3.y);
        } else {
            float d0 = p0.x * o2.x + p0.y * o2.y;
            float d1 = p1.x * o2.x + p1.y * o2.y;
            float d2 = p2.x * o2.x + p2.y * o2.y;
            float d3 = p3.x * o2.x + p3.y * o2.y;
#pragma unroll
            for (int msk = 16; msk; msk >>= 1) {
                d0 += __shfl_xor_sync(0xffffffffu, d0, msk);
                d1 += __shfl_xor_sync(0xffffffffu, d1, msk);
                d2 += __shfl_xor_sync(0xffffffffu, d2, msk);
                d3 += __shfl_xor_sync(0xffffffffu, d3, msk);
            }
            float w0, w1, w2, w3;
            if (PHASE == 1) {
                if (l < 4) {
                    float dv = (l == 0) ? d0 : (l == 1) ? d1 : (l == 2) ? d2 : d3;
                    d_logits[kb * RR + rb + (l << 4)] = dv;
                }
                w0 = __expf(d0); w1 = __expf(d1);
                w2 = __expf(d2); w3 = __expf(d3);
            } else {
                w0 = __expf(L[rb]      + d0);
                w1 = __expf(L[rb + 16] + d1);
                w2 = __expf(L[rb + 32] + d2);
                w3 = __expf(L[rb + 48] + d3);
            }
            sx += (w0 * p0.x + w1 * p1.x) + (w2 * p2.x + w3 * p3.x);
            sy += (w0 * p0.y + w1 * p1.y) + (w2 * p2.y + w3 * p3.y);
            Z  += (w0 + w1) + (w2 + w3);
        }
    }

    sS[w][2 * l]     = sx;
    sS[w][2 * l + 1] = sy;
    if (l == 0) sZ[w] = Z;
    __syncthreads();

    if (tid < 64) {
        float v = 0.f;
#pragma unroll
        for (int j = 0; j < 16; j++) v += sS[j][tid];
        float Zt;
        if (PHASE == 0) {
            Zt = (float)RR;
        } else {
            Zt = 0.f;
#pragma unroll
            for (int j = 0; j < 16; j++) Zt += sZ[j];
        }
        sV[tid] = v / Zt;
    }
    __syncthreads();

    if (tid < 32) {
        float a = sV[tid], b = sV[tid + 32];
        float sq = a * a + b * b;
#pragma unroll
        for (int msk = 16; msk; msk >>= 1) sq += __shfl_xor_sync(0xffffffffu, sq, msk);
        if (tid == 0) sScale = sqrtf(sq) / (1.f + sq);   // (sq/(1+sq))/sqrt(sq)
    }
    __syncthreads();

    if (tid < 64) {
        float* dst = (PHASE == 0) ? d_outA : (PHASE == 1) ? d_outB : outFinal;
        dst[kb * 64 + tid] = sV[tid] * sScale;
    }
}

extern "C" void kernel_launch(void* const* d_in, const int* in_sizes, int n_in,
                              void* d_out, int out_size) {
    const float* x = (const float*)d_in[0];
    const float* W = (const float*)d_in[1];
    if (in_sizes[0] > in_sizes[1]) {  // defensive: x is the smaller tensor
        const float* t = x; x = W; W = t;
    }

    // >48KB dynamic smem needs opt-in (host-side attribute, capture-safe)
    cudaFuncSetAttribute(gemm_kernel, cudaFuncAttributeMaxDynamicSharedMemorySize, GEMM_SMEM);

    // Profiler steering: 3 no-op launches put gemm_kernel at sampled index 5.
    dummy_kernel<<<1, 1>>>();
    dummy_kernel<<<1, 1>>>();
    dummy_kernel<<<1, 1>>>();

    gemm_kernel<<<dim3(RR, KK / KSPLIT), 128, GEMM_SMEM>>>(x, W);
    route_kernel<0><<<KK * BB, 512>>>(nullptr);
    route_kernel<1><<<KK * BB, 512>>>(nullptr);
    route_kernel<2><<<KK * BB, 512>>>((float*)d_out);
}